// round 13
// baseline (speedup 1.0000x reference)
#include <cuda_runtime.h>
#include <cuda_fp16.h>
#include <math.h>
#include <stdint.h>

#define D_MODEL 2048
#define N_HEADS 16
#define D_HEAD 128
#define BATCH 4
#define SEQ 2048
#define M_ROWS (BATCH*SEQ)      /* 8192 */
#define N_QKV (3*D_MODEL)       /* 6144 */
#define BH (BATCH*N_HEADS)      /* 64  */

// ---------------- scratch (no allocation allowed) ----------------
__device__ __half g_Qh[(size_t)BH*SEQ*D_HEAD];
__device__ __half g_Kh[(size_t)BH*SEQ*D_HEAD];
__device__ __half g_Vh[(size_t)BH*SEQ*D_HEAD];

__device__ __half g_x16[(size_t)M_ROWS*D_MODEL];
__device__ __half g_wq16[(size_t)D_MODEL*N_QKV];
__device__ __half g_wo16[(size_t)D_MODEL*D_MODEL];
__device__ __half g_c16[(size_t)M_ROWS*D_MODEL];

// ---------------- helpers ----------------
__device__ __forceinline__ uint32_t smem_u32(const void* p) {
    return (uint32_t)__cvta_generic_to_shared(p);
}
#define CP_ASYNC16(dst, src) \
    asm volatile("cp.async.cg.shared.global [%0], [%1], 16;" :: "r"(dst), "l"(src))
#define CP_COMMIT()  asm volatile("cp.async.commit_group;" ::: "memory")
#define CP_WAITG(n)  asm volatile("cp.async.wait_group %0;" :: "n"(n) : "memory")

__device__ __forceinline__ void ldsm_x4(uint32_t (&r)[4], uint32_t addr) {
    asm volatile("ldmatrix.sync.aligned.m8n8.x4.shared.b16 {%0,%1,%2,%3}, [%4];"
                 : "=r"(r[0]), "=r"(r[1]), "=r"(r[2]), "=r"(r[3]) : "r"(addr));
}
__device__ __forceinline__ void ldsm_x4t(uint32_t (&r)[4], uint32_t addr) {
    asm volatile("ldmatrix.sync.aligned.m8n8.x4.trans.shared.b16 {%0,%1,%2,%3}, [%4];"
                 : "=r"(r[0]), "=r"(r[1]), "=r"(r[2]), "=r"(r[3]) : "r"(addr));
}
__device__ __forceinline__ void mma_fp16(float (&d)[4], const uint32_t (&a)[4],
                                         const uint32_t (&b)[2]) {
    asm volatile("mma.sync.aligned.m16n8k16.row.col.f32.f16.f16.f32 "
                 "{%0,%1,%2,%3}, {%4,%5,%6,%7}, {%8,%9}, {%0,%1,%2,%3};"
                 : "+f"(d[0]), "+f"(d[1]), "+f"(d[2]), "+f"(d[3])
                 : "r"(a[0]), "r"(a[1]), "r"(a[2]), "r"(a[3]),
                   "r"(b[0]), "r"(b[1]));
}
__device__ __forceinline__ uint32_t pack_h2(float lo, float hi) {
    __half2 h = __floats2half2_rn(lo, hi);
    return *(uint32_t*)&h;
}

// ---------------- conversion kernel ----------------
__global__ __launch_bounds__(256)
void conv_fp16_kernel(const float* __restrict__ in, __half* __restrict__ o, int n4)
{
    int idx = blockIdx.x * blockDim.x + threadIdx.x;
    if (idx >= n4) return;
    float4 v = *(const float4*)&in[idx * 4];
    __half2 a, b;
    a.x = __float2half(v.x); a.y = __float2half(v.y);
    b.x = __float2half(v.z); b.y = __float2half(v.w);
    *(__half2*)&o[idx * 4]     = a;
    *(__half2*)&o[idx * 4 + 2] = b;
}

// ---------------- tile constants (K-chunk = 64) ----------------
#define A64_STRIDE 72
#define B64_STRIDE 136
#define GA64 (128*A64_STRIDE)   /* 9216 elems */
#define GB64 (64*B64_STRIDE)    /* 8704 elems */
#define NCH64 (D_MODEL/64)      /* 32 chunks */
#define G64STAGE (GA64 + GB64)           /* 17920 elems */
#define GEMM_SMEM_BYTES (2*G64STAGE*2)   /* 71680 : 2-stage -> 3 CTAs/SM */
#define STG_STRIDE 136

// ================= 1-term fp16 GEMM (K64, 2-stage, 3 CTAs/SM) =============
template<int N_DIM>
__device__ __forceinline__ void g_load_stage(char* dsm, int buf, int k0,
    const __half* A, const __half* Bs, int row0, int col0, int tid)
{
    uint32_t base = smem_u32(dsm) + (uint32_t)buf * (G64STAGE*2);
#pragma unroll
    for (int s = 0; s < 4; s++) {
        int id = tid + s * 256;                 // 0..1023
        int ra = id >> 3, ca = id & 7;          // A: 128 rows x 8 chunks
        CP_ASYNC16(base + ra * (A64_STRIDE*2) + ca * 16,
                   A + (size_t)(row0 + ra) * D_MODEL + k0 + ca * 8);
        int rb = id >> 4, cb = id & 15;         // B: 64 rows x 16 chunks
        CP_ASYNC16(base + GA64*2 + rb * (B64_STRIDE*2) + cb * 16,
                   Bs + (size_t)(k0 + rb) * N_DIM + col0 + cb * 8);
    }
}

template<int N_DIM, bool IS_QKV>
__global__ __launch_bounds__(256, 3)
void gemm_kernel(const __half* __restrict__ A,
                 const __half* __restrict__ Bs,
                 const float* __restrict__ bias,
                 float* __restrict__ out)
{
    extern __shared__ __align__(16) char dsm[];
    const int tid  = threadIdx.x;
    const int lane = tid & 31;
    const int warp = tid >> 5;
    const int wm = warp & 1;
    const int wn = warp >> 1;
    const int row0 = blockIdx.y * 128;
    const int col0 = blockIdx.x * 128;
    const int l16 = lane & 15;
    const int lhi = lane >> 4;

    float acc[4][4][4];
#pragma unroll
    for (int i = 0; i < 4; i++)
#pragma unroll
        for (int j = 0; j < 4; j++)
#pragma unroll
            for (int k = 0; k < 4; k++) acc[i][j][k] = 0.f;

    g_load_stage<N_DIM>(dsm, 0, 0,  A, Bs, row0, col0, tid);
    CP_COMMIT();
    g_load_stage<N_DIM>(dsm, 1, 64, A, Bs, row0, col0, tid);
    CP_COMMIT();

#pragma unroll 1
    for (int c = 0; c < NCH64; c++) {
        CP_WAITG(1);          // chunk c arrived (c+1 may be pending)
        __syncthreads();

        const __half* As  = (const __half*)(dsm + (size_t)(c & 1) * G64STAGE * 2);
        const __half* Bss = As + GA64;

#pragma unroll
        for (int ksub = 0; ksub < 4; ksub++) {
            uint32_t bf[4][2];
#pragma unroll
            for (int np = 0; np < 2; np++) {
                uint32_t bk[4];
                ldsm_x4t(bk, smem_u32(&Bss[(ksub*16 + l16) * B64_STRIDE +
                                           wn*32 + (np*2 + lhi)*8]));
                bf[np*2][0]   = bk[0]; bf[np*2][1]   = bk[1];
                bf[np*2+1][0] = bk[2]; bf[np*2+1][1] = bk[3];
            }
#pragma unroll
            for (int mt = 0; mt < 4; mt++) {
                uint32_t ah[4];
                ldsm_x4(ah, smem_u32(&As[(wm*64 + mt*16 + l16) * A64_STRIDE + ksub*16 + lhi*8]));
#pragma unroll
                for (int nt = 0; nt < 4; nt++)
                    mma_fp16(acc[mt][nt], ah, bf[nt]);
            }
        }

        __syncthreads();      // all warps done reading buf (c&1)
        if (c + 2 < NCH64)
            g_load_stage<N_DIM>(dsm, c & 1, (c + 2) * 64, A, Bs, row0, col0, tid);
        CP_COMMIT();
    }

    const int g = lane >> 2, tq = lane & 3;

    if (IS_QKV) {
        // stage bias-added fp16 tile in smem
        __syncthreads();
        __half* stg = (__half*)dsm;   // 128 x STG_STRIDE
#pragma unroll
        for (int mt = 0; mt < 4; mt++) {
#pragma unroll
            for (int nt = 0; nt < 4; nt++) {
                int rr = wm*64 + mt*16 + g;
                int cc = wn*32 + nt*8 + tq*2;
                float bias0 = __ldg(&bias[col0 + cc]);
                float bias1 = __ldg(&bias[col0 + cc + 1]);
                __half2 v0, v1;
                v0.x = __float2half(acc[mt][nt][0] + bias0);
                v0.y = __float2half(acc[mt][nt][1] + bias1);
                v1.x = __float2half(acc[mt][nt][2] + bias0);
                v1.y = __float2half(acc[mt][nt][3] + bias1);
                *(__half2*)&stg[rr * STG_STRIDE + cc]       = v0;
                *(__half2*)&stg[(rr + 8) * STG_STRIDE + cc] = v1;
            }
        }
        __syncthreads();

        // this 128-col block is one head's full d-range of q/k/v
        const int which = col0 >> 11;        // 0=q 1=k 2=v
        const int h_    = (col0 & 2047) >> 7;
        __half* buf = (which == 0) ? g_Qh : ((which == 1) ? g_Kh : g_Vh);

        const int r  = tid >> 1;             // 0..127
        const int hf = tid & 1;              // half-row: cols hf*64..+63
        const int grow = row0 + r;
        const int b_ = grow >> 11;
        const int t_ = grow & 2047;
        size_t gbase = (((size_t)b_ * N_HEADS + h_) * SEQ + t_) * D_HEAD + hf * 64;
        const __half* srcrow = &stg[r * STG_STRIDE];

        if (which == 2) {
            // V: plain copy
#pragma unroll
            for (int i = 0; i < 8; i++)
                *(uint4*)&buf[gbase + i * 8] = *(const uint4*)&srcrow[hf * 64 + i * 8];
        } else {
            // Q/K: fused RoPE (same math as the old rope kernel:
            // rotate the fp16-rounded values in fp32, store fp16)
            __half tmp[64];
            const float tpos = (float)t_;
#pragma unroll
            for (int j = 0; j < 64; j++) {
                float inv = __expf(-(float)j * (9.210340371976184f / 64.0f));
                float s, cth;
                __sincosf(tpos * inv, &s, &cth);
                float x1 = __half2float(srcrow[j]);
                float x2 = __half2float(srcrow[j + 64]);
                float o = (hf == 0) ? (x1 * cth - x2 * s)
                                    : (x2 * cth + x1 * s);
                tmp[j] = __float2half(o);
            }
#pragma unroll
            for (int i = 0; i < 8; i++)
                *(uint4*)&buf[gbase + i * 8] = *(const uint4*)&tmp[i * 8];
        }
    } else {
#pragma unroll
        for (int mt = 0; mt < 4; mt++) {
#pragma unroll
            for (int nt = 0; nt < 4; nt++) {
                int r = row0 + wm*64 + mt*16 + g;
                int cc = col0 + wn*32 + nt*8 + tq*2;
                float bias0 = __ldg(&bias[cc]);
                float bias1 = __ldg(&bias[cc + 1]);
                out[(size_t)r * D_MODEL + cc]           = acc[mt][nt][0] + bias0;
                out[(size_t)r * D_MODEL + cc + 1]       = acc[mt][nt][1] + bias1;
                out[(size_t)(r + 8) * D_MODEL + cc]     = acc[mt][nt][2] + bias0;
                out[(size_t)(r + 8) * D_MODEL + cc + 1] = acc[mt][nt][3] + bias1;
            }
        }
    }
}

// ---------------- Flash attention: register-P + double-buffered K/V --------
#define TS 136
#define ATTN_Q_ELEMS (128*TS)
#define KV_ELEMS (64*TS)
#define ATTN_SMEM_BYTES ((ATTN_Q_ELEMS + 4*KV_ELEMS)*2)   /* 104448 */

__global__ __launch_bounds__(256)
void attn_mma_kernel()
{
    extern __shared__ __align__(16) char dsm[];
    __half* Qs  = (__half*)dsm;
    __half* Kb0 = Qs + ATTN_Q_ELEMS;       // K stages 0,1
    __half* Vb0 = Kb0 + 2*KV_ELEMS;        // V stages 0,1

    const int bh = blockIdx.y;
    const int qt = (SEQ/128 - 1) - blockIdx.x;   // heavy tiles first
    const int q0 = qt * 128;
    const float SC2 = 0.08838834764831845f * 1.4426950408889634f;

    const __half* Qg = g_Qh + (size_t)bh * SEQ * D_HEAD;
    const __half* Kg = g_Kh + (size_t)bh * SEQ * D_HEAD;
    const __half* Vg = g_Vh + (size_t)bh * SEQ * D_HEAD;

    const int tid = threadIdx.x;
    const int warp = tid >> 5, lane = tid & 31;
    const int m0 = warp * 16;
    const int l16 = lane & 15, lhi = lane >> 4;
    const int g = lane >> 2, tq = lane & 3;

    // Q tile load
    for (int i = tid; i < 128 * 16; i += 256) {
        int r = i >> 4, c16 = i & 15;
        CP_ASYNC16(smem_u32(&Qs[r * TS + c16 * 8]),
                   &Qg[(size_t)(q0 + r) * D_HEAD + c16 * 8]);
    }
    CP_COMMIT();

    const int ktiles = 2 * qt + 2;

    // KV stage 0
    for (int i = tid; i < 64 * 16; i += 256) {
        int r = i >> 4, c16 = i & 15;
        size_t goff = (size_t)r * D_HEAD + c16 * 8;
        CP_ASYNC16(smem_u32(&Kb0[r * TS + c16 * 8]), &Kg[goff]);
        CP_ASYNC16(smem_u32(&Vb0[r * TS + c16 * 8]), &Vg[goff]);
    }
    CP_COMMIT();

    float mI0 = -INFINITY, mI1 = -INFINITY, lI0 = 0.f, lI1 = 0.f;
    float ctx[16][4];
#pragma unroll
    for (int i = 0; i < 16; i++)
#pragma unroll
        for (int j = 0; j < 4; j++) ctx[i][j] = 0.f;

#pragma unroll 1
    for (int kt = 0; kt < ktiles; kt++) {
        const int buf = kt & 1;
        __syncthreads();   // all warps done reading buf^1 (iteration kt-1)

        if (kt + 1 < ktiles) {
            const int kb1 = (kt + 1) * 64;
            __half* Kd = Kb0 + (buf ^ 1) * KV_ELEMS;
            __half* Vd = Vb0 + (buf ^ 1) * KV_ELEMS;
            for (int i = tid; i < 64 * 16; i += 256) {
                int r = i >> 4, c16 = i & 15;
                size_t goff = (size_t)(kb1 + r) * D_HEAD + c16 * 8;
                CP_ASYNC16(smem_u32(&Kd[r * TS + c16 * 8]), &Kg[goff]);
                CP_ASYNC16(smem_u32(&Vd[r * TS + c16 * 8]), &Vg[goff]);
            }
        }
        CP_COMMIT();
        CP_WAITG(1);       // FIFO: stage kt retired, kt+1 may stay in flight
        __syncthreads();   // publish stage kt to all warps

        const __half* Ks = Kb0 + buf * KV_ELEMS;
        const __half* Vs = Vb0 + buf * KV_ELEMS;
        const int kb = kt * 64;

        // ---- scores S = Q @ K^T ----
        float sacc[8][4];
#pragma unroll
        for (int nt = 0; nt < 8; nt++)
#pragma unroll
            for (int e = 0; e < 4; e++) sacc[nt][e] = 0.f;

        const int krow = lane & 7;
        const int kpair = (lane >> 4) & 1;
        const int kcolsel = ((lane >> 3) & 1) * 8;
#pragma unroll
        for (int ks = 0; ks < 8; ks++) {
            uint32_t ah[4];
            ldsm_x4(ah, smem_u32(&Qs[(m0 + l16) * TS + ks * 16 + lhi * 8]));
#pragma unroll
            for (int np = 0; np < 4; np++) {
                uint32_t bk[4];
                ldsm_x4(bk, smem_u32(&Ks[((np * 2 + kpair) * 8 + krow) * TS +
                                         ks * 16 + kcolsel]));
                uint32_t b0[2] = { bk[0], bk[1] };
                uint32_t b1[2] = { bk[2], bk[3] };
                mma_fp16(sacc[np * 2],     ah, b0);
                mma_fp16(sacc[np * 2 + 1], ah, b1);
            }
        }

        // ---- online softmax (base-2); p stays in sacc ----
        const bool diag = (kt >= ktiles - 2);
        const int r0 = q0 + m0 + g, r1 = r0 + 8;
        float rm0 = -INFINITY, rm1 = -INFINITY;
#pragma unroll
        for (int nt = 0; nt < 8; nt++) {
            int cb0 = kb + nt * 8 + tq * 2;
            float s0 = sacc[nt][0] * SC2, s1 = sacc[nt][1] * SC2;
            float s2 = sacc[nt][2] * SC2, s3 = sacc[nt][3] * SC2;
            if (diag) {
                if (cb0     > r0) s0 = -INFINITY;
                if (cb0 + 1 > r0) s1 = -INFINITY;
                if (cb0     > r1) s2 = -INFINITY;
                if (cb0 + 1 > r1) s3 = -INFINITY;
            }
            sacc[nt][0] = s0; sacc[nt][1] = s1; sacc[nt][2] = s2; sacc[nt][3] = s3;
            rm0 = fmaxf(rm0, fmaxf(s0, s1));
            rm1 = fmaxf(rm1, fmaxf(s2, s3));
        }
        rm0 = fmaxf(rm0, __shfl_xor_sync(0xffffffffu, rm0, 1));
        rm0 = fmaxf(rm0, __shfl_xor_sync(0xffffffffu, rm0, 2));
        rm1 = fmaxf(rm1, __shfl_xor_sync(0xffffffffu, rm1, 1));
        rm1 = fmaxf(rm1, __shfl_xor_sync(0xffffffffu, rm1, 2));
        float mn0 = fmaxf(mI0, rm0), mn1 = fmaxf(mI1, rm1);
        float c0 = exp2f(mI0 - mn0), c1 = exp2f(mI1 - mn1);
        float ps0 = 0.f, ps1 = 0.f;
#pragma unroll
        for (int nt = 0; nt < 8; nt++) {
            float p0 = exp2f(sacc[nt][0] - mn0);
            float p1 = exp2f(sacc[nt][1] - mn0);
            float p2 = exp2f(sacc[nt][2] - mn1);
            float p3 = exp2f(sacc[nt][3] - mn1);
            sacc[nt][0] = p0; sacc[nt][1] = p1;
            sacc[nt][2] = p2; sacc[nt][3] = p3;
            ps0 += p0 + p1; ps1 += p2 + p3;
        }
        ps0 += __shfl_xor_sync(0xffffffffu, ps0, 1);
        ps0 += __shfl_xor_sync(0xffffffffu, ps0, 2);
        ps1 += __shfl_xor_sync(0xffffffffu, ps1, 1);
        ps1 += __shfl_xor_sync(0xffffffffu, ps1, 2);
        lI0 = lI0 * c0 + ps0; lI1 = lI1 * c1 + ps1;
        mI0 = mn0; mI1 = mn1;
#pragma unroll
        for (int n2 = 0; n2 < 16; n2++) {
            ctx[n2][0] *= c0; ctx[n2][1] *= c0;
            ctx[n2][2] *= c1; ctx[n2][3] *= c1;
        }

        // ---- ctx += P @ V; P packed from registers ----
        const int vpair = lane >> 4;
#pragma unroll
        for (int ks = 0; ks < 4; ks++) {
            uint32_t aph[4];
            aph[0] = pack_h2(sacc[2*ks][0],     sacc[2*ks][1]);
            aph[1] = pack_h2(sacc[2*ks][2],     sacc[2*ks][3]);
            aph[2] = pack_h2(sacc[2*ks + 1][0], sacc[2*ks + 1][1]);
            aph[3] = pack_h2(sacc[2*ks + 1][2], sacc[2*ks + 1][3]);
#pragma unroll
            for (int np = 0; np < 8; np++) {
                uint32_t bv[4];
                ldsm_x4t(bv, smem_u32(&Vs[(ks * 16 + l16) * TS +
                                          (np * 2 + vpair) * 8]));
                uint32_t b0[2] = { bv[0], bv[1] };
                uint32_t b1[2] = { bv[2], bv[3] };
                mma_fp16(ctx[np * 2],     aph, b0);
                mma_fp16(ctx[np * 2 + 1], aph, b1);
            }
        }
    }

    // ---- epilogue: normalize, single fp16 ctx write (b*t, d_model) ----
    float ri0 = 1.0f / lI0, ri1 = 1.0f / lI1;
    const int b_ = bh >> 4, h_ = bh & 15;
    const int t0 = q0 + m0 + g, t1 = t0 + 8;
#pragma unroll
    for (int nt = 0; nt < 16; nt++) {
        int col = h_ * D_HEAD + nt * 8 + tq * 2;
        {
            __half2 hh;
            hh.x = __float2half(ctx[nt][0] * ri0);
            hh.y = __float2half(ctx[nt][1] * ri0);
            *(__half2*)&g_c16[(size_t)(b_ * SEQ + t0) * D_MODEL + col] = hh;
        }
        {
            __half2 hh;
            hh.x = __float2half(ctx[nt][2] * ri1);
            hh.y = __float2half(ctx[nt][3] * ri1);
            *(__half2*)&g_c16[(size_t)(b_ * SEQ + t1) * D_MODEL + col] = hh;
        }
    }
}

// ---------------- launcher ----------------
extern "C" void kernel_launch(void* const* d_in, const int* in_sizes, int n_in,
                              void* d_out, int out_size)
{
    const float* x     = (const float*)d_in[0];
    const float* w_qkv = (const float*)d_in[1];
    const float* b_qkv = (const float*)d_in[2];
    const float* w_out = (const float*)d_in[3];
    const float* b_out = (const float*)d_in[4];
    float* out = (float*)d_out;

    (void)in_sizes; (void)n_in; (void)out_size;

    __half *x16, *wq, *wo, *c16;
    cudaGetSymbolAddress((void**)&x16, g_x16);
    cudaGetSymbolAddress((void**)&wq,  g_wq16);
    cudaGetSymbolAddress((void**)&wo,  g_wo16);
    cudaGetSymbolAddress((void**)&c16, g_c16);

    // 0) conversions (single fp16)
    {
        int n4 = M_ROWS * D_MODEL / 4;
        conv_fp16_kernel<<<(n4 + 255) / 256, 256>>>(x, x16, n4);
        n4 = D_MODEL * N_QKV / 4;
        conv_fp16_kernel<<<(n4 + 255) / 256, 256>>>(w_qkv, wq, n4);
        n4 = D_MODEL * D_MODEL / 4;
        conv_fp16_kernel<<<(n4 + 255) / 256, 256>>>(w_out, wo, n4);
    }
    // 1) QKV projection (1-term fp16, K64, 2-stage, 3 CTAs/SM, fused RoPE)
    {
        cudaFuncSetAttribute(gemm_kernel<N_QKV, true>,
                             cudaFuncAttributeMaxDynamicSharedMemorySize, GEMM_SMEM_BYTES);
        dim3 grid(N_QKV / 128, M_ROWS / 128);
        gemm_kernel<N_QKV, true><<<grid, 256, GEMM_SMEM_BYTES>>>(x16, wq, b_qkv, nullptr);
    }
    // 2) Flash attention (register-P, double-buffered K/V)
    {
        cudaFuncSetAttribute(attn_mma_kernel,
                             cudaFuncAttributeMaxDynamicSharedMemorySize, ATTN_SMEM_BYTES);
        dim3 grid(SEQ / 128, BH);
        attn_mma_kernel<<<grid, 256, ATTN_SMEM_BYTES>>>();
    }
    // 3) Output projection (1-term fp16, K64, 2-stage, 3 CTAs/SM)
    {
        cudaFuncSetAttribute(gemm_kernel<D_MODEL, false>,
                             cudaFuncAttributeMaxDynamicSharedMemorySize, GEMM_SMEM_BYTES);
        dim3 grid(D_MODEL / 128, M_ROWS / 128);
        gemm_kernel<D_MODEL, false><<<grid, 256, GEMM_SMEM_BYTES>>>(c16, wo, b_out, out);
    }
}

// round 14
// speedup vs baseline: 1.4678x; 1.4678x over previous
#include <cuda_runtime.h>
#include <cuda_fp16.h>
#include <math.h>
#include <stdint.h>

#define D_MODEL 2048
#define N_HEADS 16
#define D_HEAD 128
#define BATCH 4
#define SEQ 2048
#define M_ROWS (BATCH*SEQ)      /* 8192 */
#define N_QKV (3*D_MODEL)       /* 6144 */
#define BH (BATCH*N_HEADS)      /* 64  */

// ---------------- scratch (no allocation allowed) ----------------
__device__ __half g_Qh[(size_t)BH*SEQ*D_HEAD];
__device__ __half g_Kh[(size_t)BH*SEQ*D_HEAD];
__device__ __half g_Vh[(size_t)BH*SEQ*D_HEAD];

__device__ __half g_x16[(size_t)M_ROWS*D_MODEL];
__device__ __half g_wq16[(size_t)D_MODEL*N_QKV];
__device__ __half g_wo16[(size_t)D_MODEL*D_MODEL];
__device__ __half g_c16[(size_t)M_ROWS*D_MODEL];

// ---------------- helpers ----------------
__device__ __forceinline__ uint32_t smem_u32(const void* p) {
    return (uint32_t)__cvta_generic_to_shared(p);
}
#define CP_ASYNC16(dst, src) \
    asm volatile("cp.async.cg.shared.global [%0], [%1], 16;" :: "r"(dst), "l"(src))
#define CP_COMMIT()  asm volatile("cp.async.commit_group;" ::: "memory")
#define CP_WAITG(n)  asm volatile("cp.async.wait_group %0;" :: "n"(n) : "memory")

__device__ __forceinline__ void ldsm_x4(uint32_t (&r)[4], uint32_t addr) {
    asm volatile("ldmatrix.sync.aligned.m8n8.x4.shared.b16 {%0,%1,%2,%3}, [%4];"
                 : "=r"(r[0]), "=r"(r[1]), "=r"(r[2]), "=r"(r[3]) : "r"(addr));
}
__device__ __forceinline__ void ldsm_x4t(uint32_t (&r)[4], uint32_t addr) {
    asm volatile("ldmatrix.sync.aligned.m8n8.x4.trans.shared.b16 {%0,%1,%2,%3}, [%4];"
                 : "=r"(r[0]), "=r"(r[1]), "=r"(r[2]), "=r"(r[3]) : "r"(addr));
}
__device__ __forceinline__ void mma_fp16(float (&d)[4], const uint32_t (&a)[4],
                                         const uint32_t (&b)[2]) {
    asm volatile("mma.sync.aligned.m16n8k16.row.col.f32.f16.f16.f32 "
                 "{%0,%1,%2,%3}, {%4,%5,%6,%7}, {%8,%9}, {%0,%1,%2,%3};"
                 : "+f"(d[0]), "+f"(d[1]), "+f"(d[2]), "+f"(d[3])
                 : "r"(a[0]), "r"(a[1]), "r"(a[2]), "r"(a[3]),
                   "r"(b[0]), "r"(b[1]));
}
__device__ __forceinline__ uint32_t pack_h2(float lo, float hi) {
    __half2 h = __floats2half2_rn(lo, hi);
    return *(uint32_t*)&h;
}

// ---------------- conversion kernel ----------------
__global__ __launch_bounds__(256)
void conv_fp16_kernel(const float* __restrict__ in, __half* __restrict__ o, int n4)
{
    int idx = blockIdx.x * blockDim.x + threadIdx.x;
    if (idx >= n4) return;
    float4 v = *(const float4*)&in[idx * 4];
    __half2 a, b;
    a.x = __float2half(v.x); a.y = __float2half(v.y);
    b.x = __float2half(v.z); b.y = __float2half(v.w);
    *(__half2*)&o[idx * 4]     = a;
    *(__half2*)&o[idx * 4 + 2] = b;
}

// ---------------- tile constants (K-chunk = 64) ----------------
#define A64_STRIDE 72
#define B64_STRIDE 136
#define GA64 (128*A64_STRIDE)   /* 9216 elems */
#define GB64 (64*B64_STRIDE)    /* 8704 elems */
#define NCH64 (D_MODEL/64)      /* 32 chunks */
#define G64STAGE (GA64 + GB64)           /* 17920 elems */
#define GEMM_SMEM_BYTES (3*G64STAGE*2)   /* 107520 : 3-stage, 2 CTAs/SM */
#define STG_STRIDE 136

// ================= 1-term fp16 GEMM (K64, 3-stage) =============
template<int N_DIM>
__device__ __forceinline__ void g_load_stage(char* dsm, int buf, int k0,
    const __half* A, const __half* Bs, int row0, int col0, int tid)
{
    uint32_t base = smem_u32(dsm) + (uint32_t)buf * (G64STAGE*2);
#pragma unroll
    for (int s = 0; s < 4; s++) {
        int id = tid + s * 256;                 // 0..1023
        int ra = id >> 3, ca = id & 7;          // A: 128 rows x 8 chunks
        CP_ASYNC16(base + ra * (A64_STRIDE*2) + ca * 16,
                   A + (size_t)(row0 + ra) * D_MODEL + k0 + ca * 8);
        int rb = id >> 4, cb = id & 15;         // B: 64 rows x 16 chunks
        CP_ASYNC16(base + GA64*2 + rb * (B64_STRIDE*2) + cb * 16,
                   Bs + (size_t)(k0 + rb) * N_DIM + col0 + cb * 8);
    }
}

template<int N_DIM, bool IS_QKV>
__global__ __launch_bounds__(256)
void gemm_kernel(const __half* __restrict__ A,
                 const __half* __restrict__ Bs,
                 const float* __restrict__ bias,
                 float* __restrict__ out)
{
    extern __shared__ __align__(16) char dsm[];
    const int tid  = threadIdx.x;
    const int lane = tid & 31;
    const int warp = tid >> 5;
    const int wm = warp & 1;
    const int wn = warp >> 1;
    const int row0 = blockIdx.y * 128;
    const int col0 = blockIdx.x * 128;
    const int l16 = lane & 15;
    const int lhi = lane >> 4;

    float acc[4][4][4];
#pragma unroll
    for (int i = 0; i < 4; i++)
#pragma unroll
        for (int j = 0; j < 4; j++)
#pragma unroll
            for (int k = 0; k < 4; k++) acc[i][j][k] = 0.f;

    g_load_stage<N_DIM>(dsm, 0, 0,  A, Bs, row0, col0, tid);
    CP_COMMIT();
    g_load_stage<N_DIM>(dsm, 1, 64, A, Bs, row0, col0, tid);
    CP_COMMIT();

    int bufc = 0;
#pragma unroll 1
    for (int c = 0; c < NCH64; c++) {
        CP_WAITG(1);
        __syncthreads();

        int bufl = bufc + 2; if (bufl >= 3) bufl -= 3;
        if (c + 2 < NCH64)
            g_load_stage<N_DIM>(dsm, bufl, (c + 2) * 64, A, Bs, row0, col0, tid);
        CP_COMMIT();

        const __half* As  = (const __half*)(dsm + (size_t)bufc * G64STAGE * 2);
        const __half* Bss = As + GA64;

#pragma unroll
        for (int ksub = 0; ksub < 4; ksub++) {
            uint32_t bf[4][2];
#pragma unroll
            for (int np = 0; np < 2; np++) {
                uint32_t bk[4];
                ldsm_x4t(bk, smem_u32(&Bss[(ksub*16 + l16) * B64_STRIDE +
                                           wn*32 + (np*2 + lhi)*8]));
                bf[np*2][0]   = bk[0]; bf[np*2][1]   = bk[1];
                bf[np*2+1][0] = bk[2]; bf[np*2+1][1] = bk[3];
            }
#pragma unroll
            for (int mt = 0; mt < 4; mt++) {
                uint32_t ah[4];
                ldsm_x4(ah, smem_u32(&As[(wm*64 + mt*16 + l16) * A64_STRIDE + ksub*16 + lhi*8]));
#pragma unroll
                for (int nt = 0; nt < 4; nt++)
                    mma_fp16(acc[mt][nt], ah, bf[nt]);
            }
        }
        bufc++; if (bufc >= 3) bufc = 0;
    }

    const int g = lane >> 2, tq = lane & 3;

    if (IS_QKV) {
        // stage bias-added fp16 tile in smem
        __syncthreads();
        __half* stg = (__half*)dsm;   // 128 x STG_STRIDE
#pragma unroll
        for (int mt = 0; mt < 4; mt++) {
#pragma unroll
            for (int nt = 0; nt < 4; nt++) {
                int rr = wm*64 + mt*16 + g;
                int cc = wn*32 + nt*8 + tq*2;
                float bias0 = __ldg(&bias[col0 + cc]);
                float bias1 = __ldg(&bias[col0 + cc + 1]);
                __half2 v0, v1;
                v0.x = __float2half(acc[mt][nt][0] + bias0);
                v0.y = __float2half(acc[mt][nt][1] + bias1);
                v1.x = __float2half(acc[mt][nt][2] + bias0);
                v1.y = __float2half(acc[mt][nt][3] + bias1);
                *(__half2*)&stg[rr * STG_STRIDE + cc]       = v0;
                *(__half2*)&stg[(rr + 8) * STG_STRIDE + cc] = v1;
            }
        }
        __syncthreads();

        // this 128-col block is one head's full d-range of q/k/v
        const int which = col0 >> 11;        // 0=q 1=k 2=v
        const int h_    = (col0 & 2047) >> 7;
        __half* buf = (which == 0) ? g_Qh : ((which == 1) ? g_Kh : g_Vh);

        const int r  = tid >> 1;             // 0..127
        const int hf = tid & 1;              // half-row: cols hf*64..+63
        const int grow = row0 + r;
        const int b_ = grow >> 11;
        const int t_ = grow & 2047;
        size_t gbase = (((size_t)b_ * N_HEADS + h_) * SEQ + t_) * D_HEAD + hf * 64;
        const __half* srcrow = &stg[r * STG_STRIDE];

        if (which == 2) {
            // V: plain copy
#pragma unroll
            for (int i = 0; i < 8; i++)
                *(uint4*)&buf[gbase + i * 8] = *(const uint4*)&srcrow[hf * 64 + i * 8];
        } else {
            // Q/K: fused RoPE (rotate the fp16-rounded values in fp32, store fp16)
            __half tmp[64];
            const float tpos = (float)t_;
#pragma unroll
            for (int j = 0; j < 64; j++) {
                float inv = __expf(-(float)j * (9.210340371976184f / 64.0f));
                float s, cth;
                __sincosf(tpos * inv, &s, &cth);
                float x1 = __half2float(srcrow[j]);
                float x2 = __half2float(srcrow[j + 64]);
                float o = (hf == 0) ? (x1 * cth - x2 * s)
                                    : (x2 * cth + x1 * s);
                tmp[j] = __float2half(o);
            }
#pragma unroll
            for (int i = 0; i < 8; i++)
                *(uint4*)&buf[gbase + i * 8] = *(const uint4*)&tmp[i * 8];
        }
    } else {
#pragma unroll
        for (int mt = 0; mt < 4; mt++) {
#pragma unroll
            for (int nt = 0; nt < 4; nt++) {
                int r = row0 + wm*64 + mt*16 + g;
                int cc = col0 + wn*32 + nt*8 + tq*2;
                float bias0 = __ldg(&bias[cc]);
                float bias1 = __ldg(&bias[cc + 1]);
                out[(size_t)r * D_MODEL + cc]           = acc[mt][nt][0] + bias0;
                out[(size_t)r * D_MODEL + cc + 1]       = acc[mt][nt][1] + bias1;
                out[(size_t)(r + 8) * D_MODEL + cc]     = acc[mt][nt][2] + bias0;
                out[(size_t)(r + 8) * D_MODEL + cc + 1] = acc[mt][nt][3] + bias1;
            }
        }
    }
}

// ---------------- Flash attention: register-P + double-buffered K/V --------
#define TS 136
#define ATTN_Q_ELEMS (128*TS)
#define KV_ELEMS (64*TS)
#define ATTN_SMEM_BYTES ((ATTN_Q_ELEMS + 4*KV_ELEMS)*2)   /* 104448 */

__global__ __launch_bounds__(256)
void attn_mma_kernel()
{
    extern __shared__ __align__(16) char dsm[];
    __half* Qs  = (__half*)dsm;
    __half* Kb0 = Qs + ATTN_Q_ELEMS;       // K stages 0,1
    __half* Vb0 = Kb0 + 2*KV_ELEMS;        // V stages 0,1

    const int bh = blockIdx.y;
    const int qt = (SEQ/128 - 1) - blockIdx.x;   // heavy tiles first
    const int q0 = qt * 128;
    const float SC2 = 0.08838834764831845f * 1.4426950408889634f;

    const __half* Qg = g_Qh + (size_t)bh * SEQ * D_HEAD;
    const __half* Kg = g_Kh + (size_t)bh * SEQ * D_HEAD;
    const __half* Vg = g_Vh + (size_t)bh * SEQ * D_HEAD;

    const int tid = threadIdx.x;
    const int warp = tid >> 5, lane = tid & 31;
    const int m0 = warp * 16;
    const int l16 = lane & 15, lhi = lane >> 4;
    const int g = lane >> 2, tq = lane & 3;

    // Q tile load
    for (int i = tid; i < 128 * 16; i += 256) {
        int r = i >> 4, c16 = i & 15;
        CP_ASYNC16(smem_u32(&Qs[r * TS + c16 * 8]),
                   &Qg[(size_t)(q0 + r) * D_HEAD + c16 * 8]);
    }
    CP_COMMIT();

    const int ktiles = 2 * qt + 2;

    // KV stage 0
    for (int i = tid; i < 64 * 16; i += 256) {
        int r = i >> 4, c16 = i & 15;
        size_t goff = (size_t)r * D_HEAD + c16 * 8;
        CP_ASYNC16(smem_u32(&Kb0[r * TS + c16 * 8]), &Kg[goff]);
        CP_ASYNC16(smem_u32(&Vb0[r * TS + c16 * 8]), &Vg[goff]);
    }
    CP_COMMIT();

    float mI0 = -INFINITY, mI1 = -INFINITY, lI0 = 0.f, lI1 = 0.f;
    float ctx[16][4];
#pragma unroll
    for (int i = 0; i < 16; i++)
#pragma unroll
        for (int j = 0; j < 4; j++) ctx[i][j] = 0.f;

#pragma unroll 1
    for (int kt = 0; kt < ktiles; kt++) {
        const int buf = kt & 1;
        __syncthreads();   // all warps done reading buf^1 (iteration kt-1)

        if (kt + 1 < ktiles) {
            const int kb1 = (kt + 1) * 64;
            __half* Kd = Kb0 + (buf ^ 1) * KV_ELEMS;
            __half* Vd = Vb0 + (buf ^ 1) * KV_ELEMS;
            for (int i = tid; i < 64 * 16; i += 256) {
                int r = i >> 4, c16 = i & 15;
                size_t goff = (size_t)(kb1 + r) * D_HEAD + c16 * 8;
                CP_ASYNC16(smem_u32(&Kd[r * TS + c16 * 8]), &Kg[goff]);
                CP_ASYNC16(smem_u32(&Vd[r * TS + c16 * 8]), &Vg[goff]);
            }
        }
        CP_COMMIT();
        CP_WAITG(1);       // FIFO: stage kt retired, kt+1 may stay in flight
        __syncthreads();   // publish stage kt to all warps

        const __half* Ks = Kb0 + buf * KV_ELEMS;
        const __half* Vs = Vb0 + buf * KV_ELEMS;
        const int kb = kt * 64;

        // ---- scores S = Q @ K^T ----
        float sacc[8][4];
#pragma unroll
        for (int nt = 0; nt < 8; nt++)
#pragma unroll
            for (int e = 0; e < 4; e++) sacc[nt][e] = 0.f;

        const int krow = lane & 7;
        const int kpair = (lane >> 4) & 1;
        const int kcolsel = ((lane >> 3) & 1) * 8;
#pragma unroll
        for (int ks = 0; ks < 8; ks++) {
            uint32_t ah[4];
            ldsm_x4(ah, smem_u32(&Qs[(m0 + l16) * TS + ks * 16 + lhi * 8]));
#pragma unroll
            for (int np = 0; np < 4; np++) {
                uint32_t bk[4];
                ldsm_x4(bk, smem_u32(&Ks[((np * 2 + kpair) * 8 + krow) * TS +
                                         ks * 16 + kcolsel]));
                uint32_t b0[2] = { bk[0], bk[1] };
                uint32_t b1[2] = { bk[2], bk[3] };
                mma_fp16(sacc[np * 2],     ah, b0);
                mma_fp16(sacc[np * 2 + 1], ah, b1);
            }
        }

        // ---- online softmax (base-2); p stays in sacc ----
        const bool diag = (kt >= ktiles - 2);
        const int r0 = q0 + m0 + g, r1 = r0 + 8;
        float rm0 = -INFINITY, rm1 = -INFINITY;
#pragma unroll
        for (int nt = 0; nt < 8; nt++) {
            int cb0 = kb + nt * 8 + tq * 2;
            float s0 = sacc[nt][0] * SC2, s1 = sacc[nt][1] * SC2;
            float s2 = sacc[nt][2] * SC2, s3 = sacc[nt][3] * SC2;
            if (diag) {
                if (cb0     > r0) s0 = -INFINITY;
                if (cb0 + 1 > r0) s1 = -INFINITY;
                if (cb0     > r1) s2 = -INFINITY;
                if (cb0 + 1 > r1) s3 = -INFINITY;
            }
            sacc[nt][0] = s0; sacc[nt][1] = s1; sacc[nt][2] = s2; sacc[nt][3] = s3;
            rm0 = fmaxf(rm0, fmaxf(s0, s1));
            rm1 = fmaxf(rm1, fmaxf(s2, s3));
        }
        rm0 = fmaxf(rm0, __shfl_xor_sync(0xffffffffu, rm0, 1));
        rm0 = fmaxf(rm0, __shfl_xor_sync(0xffffffffu, rm0, 2));
        rm1 = fmaxf(rm1, __shfl_xor_sync(0xffffffffu, rm1, 1));
        rm1 = fmaxf(rm1, __shfl_xor_sync(0xffffffffu, rm1, 2));
        float mn0 = fmaxf(mI0, rm0), mn1 = fmaxf(mI1, rm1);
        float c0 = exp2f(mI0 - mn0), c1 = exp2f(mI1 - mn1);
        float ps0 = 0.f, ps1 = 0.f;
#pragma unroll
        for (int nt = 0; nt < 8; nt++) {
            float p0 = exp2f(sacc[nt][0] - mn0);
            float p1 = exp2f(sacc[nt][1] - mn0);
            float p2 = exp2f(sacc[nt][2] - mn1);
            float p3 = exp2f(sacc[nt][3] - mn1);
            sacc[nt][0] = p0; sacc[nt][1] = p1;
            sacc[nt][2] = p2; sacc[nt][3] = p3;
            ps0 += p0 + p1; ps1 += p2 + p3;
        }
        ps0 += __shfl_xor_sync(0xffffffffu, ps0, 1);
        ps0 += __shfl_xor_sync(0xffffffffu, ps0, 2);
        ps1 += __shfl_xor_sync(0xffffffffu, ps1, 1);
        ps1 += __shfl_xor_sync(0xffffffffu, ps1, 2);
        lI0 = lI0 * c0 + ps0; lI1 = lI1 * c1 + ps1;
        mI0 = mn0; mI1 = mn1;
#pragma unroll
        for (int n2 = 0; n2 < 16; n2++) {
            ctx[n2][0] *= c0; ctx[n2][1] *= c0;
            ctx[n2][2] *= c1; ctx[n2][3] *= c1;
        }

        // ---- ctx += P @ V; P packed from registers ----
        const int vpair = lane >> 4;
#pragma unroll
        for (int ks = 0; ks < 4; ks++) {
            uint32_t aph[4];
            aph[0] = pack_h2(sacc[2*ks][0],     sacc[2*ks][1]);
            aph[1] = pack_h2(sacc[2*ks][2],     sacc[2*ks][3]);
            aph[2] = pack_h2(sacc[2*ks + 1][0], sacc[2*ks + 1][1]);
            aph[3] = pack_h2(sacc[2*ks + 1][2], sacc[2*ks + 1][3]);
#pragma unroll
            for (int np = 0; np < 8; np++) {
                uint32_t bv[4];
                ldsm_x4t(bv, smem_u32(&Vs[(ks * 16 + l16) * TS +
                                          (np * 2 + vpair) * 8]));
                uint32_t b0[2] = { bv[0], bv[1] };
                uint32_t b1[2] = { bv[2], bv[3] };
                mma_fp16(ctx[np * 2],     aph, b0);
                mma_fp16(ctx[np * 2 + 1], aph, b1);
            }
        }
    }

    // ---- epilogue: normalize, single fp16 ctx write (b*t, d_model) ----
    float ri0 = 1.0f / lI0, ri1 = 1.0f / lI1;
    const int b_ = bh >> 4, h_ = bh & 15;
    const int t0 = q0 + m0 + g, t1 = t0 + 8;
#pragma unroll
    for (int nt = 0; nt < 16; nt++) {
        int col = h_ * D_HEAD + nt * 8 + tq * 2;
        {
            __half2 hh;
            hh.x = __float2half(ctx[nt][0] * ri0);
            hh.y = __float2half(ctx[nt][1] * ri0);
            *(__half2*)&g_c16[(size_t)(b_ * SEQ + t0) * D_MODEL + col] = hh;
        }
        {
            __half2 hh;
            hh.x = __float2half(ctx[nt][2] * ri1);
            hh.y = __float2half(ctx[nt][3] * ri1);
            *(__half2*)&g_c16[(size_t)(b_ * SEQ + t1) * D_MODEL + col] = hh;
        }
    }
}

// ---------------- launcher ----------------
extern "C" void kernel_launch(void* const* d_in, const int* in_sizes, int n_in,
                              void* d_out, int out_size)
{
    const float* x     = (const float*)d_in[0];
    const float* w_qkv = (const float*)d_in[1];
    const float* b_qkv = (const float*)d_in[2];
    const float* w_out = (const float*)d_in[3];
    const float* b_out = (const float*)d_in[4];
    float* out = (float*)d_out;

    (void)in_sizes; (void)n_in; (void)out_size;

    __half *x16, *wq, *wo, *c16;
    cudaGetSymbolAddress((void**)&x16, g_x16);
    cudaGetSymbolAddress((void**)&wq,  g_wq16);
    cudaGetSymbolAddress((void**)&wo,  g_wo16);
    cudaGetSymbolAddress((void**)&c16, g_c16);

    // 0) conversions (single fp16)
    {
        int n4 = M_ROWS * D_MODEL / 4;
        conv_fp16_kernel<<<(n4 + 255) / 256, 256>>>(x, x16, n4);
        n4 = D_MODEL * N_QKV / 4;
        conv_fp16_kernel<<<(n4 + 255) / 256, 256>>>(w_qkv, wq, n4);
        n4 = D_MODEL * D_MODEL / 4;
        conv_fp16_kernel<<<(n4 + 255) / 256, 256>>>(w_out, wo, n4);
    }
    // 1) QKV projection (1-term fp16, K64, 3-stage, fused RoPE epilogue)
    {
        cudaFuncSetAttribute(gemm_kernel<N_QKV, true>,
                             cudaFuncAttributeMaxDynamicSharedMemorySize, GEMM_SMEM_BYTES);
        dim3 grid(N_QKV / 128, M_ROWS / 128);
        gemm_kernel<N_QKV, true><<<grid, 256, GEMM_SMEM_BYTES>>>(x16, wq, b_qkv, nullptr);
    }
    // 2) Flash attention (register-P, double-buffered K/V)
    {
        cudaFuncSetAttribute(attn_mma_kernel,
                             cudaFuncAttributeMaxDynamicSharedMemorySize, ATTN_SMEM_BYTES);
        dim3 grid(SEQ / 128, BH);
        attn_mma_kernel<<<grid, 256, ATTN_SMEM_BYTES>>>();
    }
    // 3) Output projection (1-term fp16, K64, 3-stage)
    {
        cudaFuncSetAttribute(gemm_kernel<D_MODEL, false>,
                             cudaFuncAttributeMaxDynamicSharedMemorySize, GEMM_SMEM_BYTES);
        dim3 grid(D_MODEL / 128, M_ROWS / 128);
        gemm_kernel<D_MODEL, false><<<grid, 256, GEMM_SMEM_BYTES>>>(c16, wo, b_out, out);
    }
}